// round 1
// baseline (speedup 1.0000x reference)
#include <cuda_runtime.h>
#include <cmath>

// Problem constants
#define B_    4096
#define IN_   1024
#define F_    512
#define HID_  128
#define D_    128
#define RH_   64
#define C_    10
#define R_    16
#define CH_   1280   // C_*HID_

// ---------------- device scratch (no allocations allowed) ----------------
__device__ __align__(256) float g_w[R_][C_];
__device__ __align__(256) float g_r1[R_][RH_];
__device__ __align__(256) float g_rv[R_][D_];
__device__ __align__(256) float g_W2[R_][HID_];
__device__ __align__(256) float g_b1[R_][HID_];
__device__ __align__(256) float g_beff[R_];
__device__ __align__(256) float g_P[CH_][R_];        // P[ch][r] = w[r,c]*W2[r,h]
__device__ __align__(256) float g_Weff[R_][F_];
__device__ __align__(256) float g_WxPart[8][IN_][R_];
__device__ __align__(256) float g_WxT[IN_][R_];      // transposed: [i][r]
__device__ __align__(256) float g_cst[R_];

// ---------------- packed f32x2 helpers ----------------
__device__ __forceinline__ unsigned long long pk2(float a, float b) {
    unsigned long long r;
    asm("mov.b64 %0, {%1,%2};" : "=l"(r) : "f"(a), "f"(b));
    return r;
}
__device__ __forceinline__ void upk2(unsigned long long v, float& a, float& b) {
    asm("mov.b64 {%0,%1}, %2;" : "=f"(a), "=f"(b) : "l"(v));
}
#define FMA2(acc, a, b) asm("fma.rn.f32x2 %0, %1, %2, %0;" : "+l"(acc) : "l"(a), "l"(b))

// ============ k1: mixing weights w[r,c] and ray hidden r1[r,o] ============
__global__ void k_tiny1(const float* __restrict__ pref,
                        const float* __restrict__ wm1_w, const float* __restrict__ wm1_b,
                        const float* __restrict__ wm2_w, const float* __restrict__ wm2_b,
                        const float* __restrict__ ray0_w, const float* __restrict__ ray0_b) {
    __shared__ float sw[R_][C_];
    int t = threadIdx.x;
    if (t < R_) {
        float p0 = pref[t * 2], p1 = pref[t * 2 + 1];
        float h[16];
        #pragma unroll
        for (int j = 0; j < 16; j++) {
            float a = p0 * wm1_w[j * 2] + p1 * wm1_w[j * 2 + 1] + wm1_b[j];
            h[j] = a > 0.f ? a : 0.f;
        }
        float wr[C_]; float s = 0.f;
        #pragma unroll
        for (int c = 0; c < C_; c++) {
            float a = wm2_b[c];
            #pragma unroll
            for (int j = 0; j < 16; j++) a += h[j] * wm2_w[c * 16 + j];
            wr[c] = 1.f / (1.f + expf(-a));
            s += wr[c];
        }
        float inv = 1.f / s;
        #pragma unroll
        for (int c = 0; c < C_; c++) { wr[c] *= inv; sw[t][c] = wr[c]; g_w[t][c] = wr[c]; }
    }
    __syncthreads();
    for (int idx = t; idx < R_ * RH_; idx += blockDim.x) {
        int r = idx / RH_, o = idx % RH_;
        float p0 = pref[r * 2], p1 = pref[r * 2 + 1];
        float a = 0.f;
        #pragma unroll
        for (int c = 0; c < C_; c++) {
            float wc = sw[r][c];
            const float* rw = ray0_w + (c * RH_ + o) * 2;
            a += wc * (p0 * rw[0] + p1 * rw[1] + ray0_b[c * RH_ + o]);
        }
        g_r1[r][o] = a > 0.f ? a : 0.f;
    }
}

// ============ k2: ray2v[r,o]  (merged ray MLP output) ============
__global__ void k_tiny2(const float* __restrict__ ray2_w, const float* __restrict__ ray2_b) {
    int r = blockIdx.x, o = threadIdx.x;  // 128 threads
    __shared__ float sw[C_];
    __shared__ float sr1[RH_];
    if (o < C_)  sw[o] = g_w[r][o];
    if (o < RH_) sr1[o] = g_r1[r][o];
    __syncthreads();
    float acc = 0.f;
    #pragma unroll
    for (int c = 0; c < C_; c++) {
        const float* row = ray2_w + ((size_t)(c * D_ + o)) * RH_;
        float dot = 0.f;
        #pragma unroll 8
        for (int h = 0; h < RH_; h++) dot += sr1[h] * row[h];
        acc += sw[c] * (dot + ray2_b[c * D_ + o]);
    }
    g_rv[r][o] = acc;
}

// ============ k3: small hypernets W2[r,h] and b1[r,h] ============
__global__ void k_small(const float* __restrict__ fc2_w, const float* __restrict__ fc2_b,
                        const float* __restrict__ b1_w,  const float* __restrict__ b1_b) {
    int r = blockIdx.x & 15, kind = blockIdx.x >> 4;
    const float* Wc = kind ? b1_w : fc2_w;
    const float* bc = kind ? b1_b : fc2_b;
    int o = threadIdx.x;  // 128
    __shared__ float sw[C_];
    __shared__ float srv[D_];
    if (o < C_) sw[o] = g_w[r][o];
    srv[o] = g_rv[r][o];
    __syncthreads();
    float acc = 0.f;
    #pragma unroll
    for (int c = 0; c < C_; c++) {
        const float4* row4 = (const float4*)(Wc + ((size_t)c * HID_ + o) * D_);
        float dot = 0.f;
        #pragma unroll 8
        for (int d4 = 0; d4 < D_ / 4; d4++) {
            float4 v = __ldg(row4 + d4);
            dot += v.x * srv[d4 * 4] + v.y * srv[d4 * 4 + 1]
                 + v.z * srv[d4 * 4 + 2] + v.w * srv[d4 * 4 + 3];
        }
        acc += sw[c] * (dot + bc[c * HID_ + o]);
    }
    if (kind) g_b1[r][o] = acc; else g_W2[r][o] = acc;
}

// ============ k4: b2/beff + P[ch][r] ============
__global__ void k_prep(const float* __restrict__ b2_w, const float* __restrict__ b2_b) {
    int t = threadIdx.x;  // 512 threads
    if (t < R_) {
        float acc = 0.f;
        #pragma unroll
        for (int c = 0; c < C_; c++) {
            float dot = 0.f;
            #pragma unroll 8
            for (int d = 0; d < D_; d++) dot += g_rv[t][d] * b2_w[c * D_ + d];
            acc += g_w[t][c] * (dot + b2_b[c]);
        }
        float be = acc;
        #pragma unroll 8
        for (int h = 0; h < HID_; h++) be += g_W2[t][h] * g_b1[t][h];
        g_beff[t] = be;
    }
    for (int idx = t; idx < CH_ * R_; idx += blockDim.x) {
        int ch = idx >> 4, r = idx & 15;
        g_P[ch][r] = g_w[r][ch >> 7] * g_W2[r][ch & 127];
    }
}

// ============ k5: THE big kernel — stream fc1_w (335 MB) -> Weff ============
// Weff[r,f] = sum_{ch,d} P[ch][r] * rv[r][d] * fc1_w[c, h*F+f, d]
// One block per f. 8 warps; each warp handles 4 consecutive ch rows per
// iteration (4 x 512B loads in flight per warp for DRAM MLP).
__global__ void __launch_bounds__(256, 2) k_weff(const float* __restrict__ fc1_w) {
    int f = blockIdx.x;
    int warp = threadIdx.x >> 5, lane = threadIdx.x & 31;
    unsigned long long acc[8][4];
    #pragma unroll
    for (int rp = 0; rp < 8; rp++)
        #pragma unroll
        for (int j = 0; j < 4; j++) acc[rp][j] = 0ull;

    for (int cb = warp * 4; cb < CH_; cb += 32) {
        float4 v[4];
        #pragma unroll
        for (int q = 0; q < 4; q++) {
            int ch = cb + q;
            int c = ch >> 7, h = ch & 127;
            const float4* p = (const float4*)(fc1_w +
                (((size_t)c * 65536u + (size_t)h * 512u + (size_t)f) << 7)) + lane;
            v[q] = __ldg(p);
        }
        #pragma unroll
        for (int q = 0; q < 4; q++) {
            int ch = cb + q;
            unsigned long long vx = pk2(v[q].x, v[q].x), vy = pk2(v[q].y, v[q].y);
            unsigned long long vz = pk2(v[q].z, v[q].z), vw = pk2(v[q].w, v[q].w);
            const unsigned long long* pp = (const unsigned long long*)g_P[ch];
            #pragma unroll
            for (int rp = 0; rp < 8; rp++) {
                unsigned long long t = __ldg(pp + rp);  // {P[ch][2rp], P[ch][2rp+1]}
                FMA2(acc[rp][0], vx, t);
                FMA2(acc[rp][1], vy, t);
                FMA2(acc[rp][2], vz, t);
                FMA2(acc[rp][3], vw, t);
            }
        }
    }
    // epilogue: multiply by rv[r][d] for this lane's d's, then reduce
    float accr[16];
    #pragma unroll
    for (int r = 0; r < 16; r++) accr[r] = 0.f;
    int d0 = lane * 4;
    #pragma unroll
    for (int rp = 0; rp < 8; rp++) {
        #pragma unroll
        for (int j = 0; j < 4; j++) {
            float a0, a1; upk2(acc[rp][j], a0, a1);
            accr[2 * rp]     += a0 * g_rv[2 * rp][d0 + j];
            accr[2 * rp + 1] += a1 * g_rv[2 * rp + 1][d0 + j];
        }
    }
    #pragma unroll
    for (int off = 16; off > 0; off >>= 1)
        #pragma unroll
        for (int r = 0; r < 16; r++)
            accr[r] += __shfl_down_sync(0xffffffffu, accr[r], off);
    __shared__ float sred[8][16];
    if (lane == 0) {
        #pragma unroll
        for (int r = 0; r < 16; r++) sred[warp][r] = accr[r];
    }
    __syncthreads();
    if (threadIdx.x < 16) {
        float s = 0.f;
        #pragma unroll
        for (int w = 0; w < 8; w++) s += sred[w][threadIdx.x];
        g_Weff[threadIdx.x][f] = s;
    }
}

// ============ k5b: add fc1_b bias contribution into Weff ============
__global__ void __launch_bounds__(128) k_weff_bias(const float* __restrict__ fc1_b) {
    int f = blockIdx.x, t = threadIdx.x;
    unsigned long long acc[8];
    #pragma unroll
    for (int rp = 0; rp < 8; rp++) acc[rp] = 0ull;
    for (int ch = t; ch < CH_; ch += 128) {
        float v = __ldg(fc1_b + (size_t)(ch >> 7) * 65536u + (size_t)(ch & 127) * 512u + f);
        unsigned long long vv = pk2(v, v);
        const unsigned long long* pp = (const unsigned long long*)g_P[ch];
        #pragma unroll
        for (int rp = 0; rp < 8; rp++) {
            unsigned long long tt = __ldg(pp + rp);
            FMA2(acc[rp], vv, tt);
        }
    }
    float accr[16];
    #pragma unroll
    for (int rp = 0; rp < 8; rp++) upk2(acc[rp], accr[2 * rp], accr[2 * rp + 1]);
    #pragma unroll
    for (int off = 16; off > 0; off >>= 1)
        #pragma unroll
        for (int r = 0; r < 16; r++)
            accr[r] += __shfl_down_sync(0xffffffffu, accr[r], off);
    __shared__ float sred[4][16];
    int warp = t >> 5, lane = t & 31;
    if (lane == 0) {
        #pragma unroll
        for (int r = 0; r < 16; r++) sred[warp][r] = accr[r];
    }
    __syncthreads();
    if (t < 16) {
        float s = sred[0][t] + sred[1][t] + sred[2][t] + sred[3][t];
        g_Weff[t][f] += s;
    }
}

// ============ k6: fold Weff into base_w -> Wx (partials over f-chunks) ============
__global__ void __launch_bounds__(128) k_wx(const float* __restrict__ base_w) {
    __shared__ __align__(16) float sW[64][16];
    int i = blockIdx.x * 128 + threadIdx.x;
    int f0 = blockIdx.y * 64;
    for (int idx = threadIdx.x; idx < 64 * 16; idx += 128) {
        int ff = idx >> 4, r = idx & 15;
        sW[ff][r] = g_Weff[r][f0 + ff];
    }
    __syncthreads();
    unsigned long long acc[8];
    #pragma unroll
    for (int rp = 0; rp < 8; rp++) acc[rp] = 0ull;
    #pragma unroll 4
    for (int ff = 0; ff < 64; ff++) {
        float bw = __ldg(base_w + (size_t)(f0 + ff) * IN_ + i);
        unsigned long long b2 = pk2(bw, bw);
        const unsigned long long* pw = (const unsigned long long*)sW[ff];
        #pragma unroll
        for (int rp = 0; rp < 8; rp++) {
            unsigned long long t = pw[rp];
            FMA2(acc[rp], b2, t);
        }
    }
    float* o = &g_WxPart[blockIdx.y][i][0];
    #pragma unroll
    for (int rp = 0; rp < 8; rp++) {
        float a, b; upk2(acc[rp], a, b);
        o[2 * rp] = a; o[2 * rp + 1] = b;
    }
}

// ============ k6b: reduce Wx partials + cst[r] ============
__global__ void k_wx_reduce(const float* __restrict__ base_b) {
    int idx = blockIdx.x * 256 + threadIdx.x;  // 64 blocks x 256 = 16384 = IN_*R_
    if (idx < IN_ * R_) {
        int i = idx >> 4, r = idx & 15;
        float s = 0.f;
        #pragma unroll
        for (int p = 0; p < 8; p++) s += g_WxPart[p][i][r];
        g_WxT[i][r] = s;
    }
    if (blockIdx.x == 0 && threadIdx.x < R_) {
        int r = threadIdx.x;
        float s = g_beff[r];
        #pragma unroll 8
        for (int f = 0; f < F_; f++) s += g_Weff[r][f] * base_b[f];
        g_cst[r] = s;
    }
}

// ============ k7: out[r,b] = x[b,:] . Wx[r,:] + cst[r]; sigmoid + raw ============
__global__ void __launch_bounds__(256) k_out(const float* __restrict__ x,
                                             float* __restrict__ out, int write_raw) {
    int warp = threadIdx.x >> 5, lane = threadIdx.x & 31;
    int b = blockIdx.x * 8 + warp;
    unsigned long long acc[8];
    #pragma unroll
    for (int rp = 0; rp < 8; rp++) acc[rp] = 0ull;
    const float4* xr = (const float4*)(x + (size_t)b * IN_) + lane;
    const unsigned long long* wt = (const unsigned long long*)g_WxT;
    #pragma unroll
    for (int k = 0; k < 8; k++) {
        float4 xv = __ldg(xr + k * 32);
        int ib = (k * 32 + lane) * 4;
        unsigned long long vx = pk2(xv.x, xv.x), vy = pk2(xv.y, xv.y);
        unsigned long long vz = pk2(xv.z, xv.z), vw = pk2(xv.w, xv.w);
        const unsigned long long* w0 = wt + (size_t)ib * 8;
        #pragma unroll
        for (int rp = 0; rp < 8; rp++) {
            unsigned long long t0 = __ldg(w0 + rp);
            unsigned long long t1 = __ldg(w0 + 8 + rp);
            unsigned long long t2 = __ldg(w0 + 16 + rp);
            unsigned long long t3 = __ldg(w0 + 24 + rp);
            FMA2(acc[rp], vx, t0);
            FMA2(acc[rp], vy, t1);
            FMA2(acc[rp], vz, t2);
            FMA2(acc[rp], vw, t3);
        }
    }
    float accr[16];
    #pragma unroll
    for (int rp = 0; rp < 8; rp++) upk2(acc[rp], accr[2 * rp], accr[2 * rp + 1]);
    #pragma unroll
    for (int off = 16; off > 0; off >>= 1)
        #pragma unroll
        for (int r = 0; r < 16; r++)
            accr[r] += __shfl_down_sync(0xffffffffu, accr[r], off);
    if (lane == 0) {
        #pragma unroll
        for (int r = 0; r < 16; r++) {
            float v = accr[r] + g_cst[r];
            out[r * B_ + b] = 1.f / (1.f + expf(-v));
            if (write_raw) out[R_ * B_ + r * B_ + b] = v;
        }
    }
}

// ---------------- launcher ----------------
extern "C" void kernel_launch(void* const* d_in, const int* in_sizes, int n_in,
                              void* d_out, int out_size) {
    const float* x      = (const float*)d_in[0];
    const float* pref   = (const float*)d_in[1];
    const float* base_w = (const float*)d_in[2];
    const float* base_b = (const float*)d_in[3];
    const float* wm1_w  = (const float*)d_in[4];
    const float* wm1_b  = (const float*)d_in[5];
    const float* wm2_w  = (const float*)d_in[6];
    const float* wm2_b  = (const float*)d_in[7];
    const float* ray0_w = (const float*)d_in[8];
    const float* ray0_b = (const float*)d_in[9];
    const float* ray2_w = (const float*)d_in[10];
    const float* ray2_b = (const float*)d_in[11];
    const float* fc1_w  = (const float*)d_in[12];
    const float* fc1_b  = (const float*)d_in[13];
    const float* b1_w   = (const float*)d_in[14];
    const float* b1_b   = (const float*)d_in[15];
    const float* fc2_w  = (const float*)d_in[16];
    const float* fc2_b  = (const float*)d_in[17];
    const float* b2_w   = (const float*)d_in[18];
    const float* b2_b   = (const float*)d_in[19];
    float* out = (float*)d_out;
    int write_raw = (out_size >= 2 * R_ * B_) ? 1 : 0;

    k_tiny1<<<1, 64>>>(pref, wm1_w, wm1_b, wm2_w, wm2_b, ray0_w, ray0_b);
    k_tiny2<<<R_, 128>>>(ray2_w, ray2_b);
    k_small<<<32, 128>>>(fc2_w, fc2_b, b1_w, b1_b);
    k_prep<<<1, 512>>>(b2_w, b2_b);
    k_weff<<<F_, 256>>>(fc1_w);
    k_weff_bias<<<F_, 128>>>(fc1_b);
    dim3 g6(8, 8);
    k_wx<<<g6, 128>>>(base_w);
    k_wx_reduce<<<64, 256>>>(base_b);
    k_out<<<B_ / 8, 256>>>(x, out, write_raw);
}

// round 2
// speedup vs baseline: 1.9559x; 1.9559x over previous
#include <cuda_runtime.h>
#include <cmath>

// Problem constants
#define B_    4096
#define IN_   1024
#define F_    512
#define HID_  128
#define D_    128
#define RH_   64
#define C_    10
#define R_    16
#define CH_   1280   // C_*HID_

// ---------------- device scratch (no allocations allowed) ----------------
__device__ __align__(256) float g_w[R_][C_];
__device__ __align__(256) float g_r1[R_][RH_];
__device__ __align__(256) float g_rv[R_][D_];
__device__ __align__(256) float g_W2[R_][HID_];
__device__ __align__(256) float g_b1[R_][HID_];
__device__ __align__(256) float g_beff[R_];
__device__ __align__(256) float g_P[CH_][R_];        // P[ch][r] = w[r,c]*W2[r,h]
__device__ __align__(256) float g_Weff[R_][F_];
__device__ __align__(256) float g_WxPart[8][IN_][R_];
__device__ __align__(256) float g_WxT[IN_][R_];      // transposed: [i][r]
__device__ __align__(256) float g_cst[R_];

// ---------------- packed f32x2 helpers ----------------
__device__ __forceinline__ unsigned long long pk2(float a, float b) {
    unsigned long long r;
    asm("mov.b64 %0, {%1,%2};" : "=l"(r) : "f"(a), "f"(b));
    return r;
}
__device__ __forceinline__ void upk2(unsigned long long v, float& a, float& b) {
    asm("mov.b64 {%0,%1}, %2;" : "=f"(a), "=f"(b) : "l"(v));
}
#define FMA2(acc, a, b) asm("fma.rn.f32x2 %0, %1, %2, %0;" : "+l"(acc) : "l"(a), "l"(b))

// ============ k1: mixing weights w[r,c] and ray hidden r1[r,o] ============
__global__ void k_tiny1(const float* __restrict__ pref,
                        const float* __restrict__ wm1_w, const float* __restrict__ wm1_b,
                        const float* __restrict__ wm2_w, const float* __restrict__ wm2_b,
                        const float* __restrict__ ray0_w, const float* __restrict__ ray0_b) {
    __shared__ float sw[R_][C_];
    int t = threadIdx.x;  // 256
    if (t < R_) {
        float p0 = pref[t * 2], p1 = pref[t * 2 + 1];
        float h[16];
        #pragma unroll
        for (int j = 0; j < 16; j++) {
            float a = p0 * wm1_w[j * 2] + p1 * wm1_w[j * 2 + 1] + wm1_b[j];
            h[j] = a > 0.f ? a : 0.f;
        }
        float wr[C_]; float s = 0.f;
        #pragma unroll
        for (int c = 0; c < C_; c++) {
            float a = wm2_b[c];
            #pragma unroll
            for (int j = 0; j < 16; j++) a += h[j] * wm2_w[c * 16 + j];
            wr[c] = 1.f / (1.f + expf(-a));
            s += wr[c];
        }
        float inv = 1.f / s;
        #pragma unroll
        for (int c = 0; c < C_; c++) { wr[c] *= inv; sw[t][c] = wr[c]; g_w[t][c] = wr[c]; }
    }
    __syncthreads();
    for (int idx = t; idx < R_ * RH_; idx += 256) {
        int r = idx >> 6, o = idx & 63;
        float p0 = pref[r * 2], p1 = pref[r * 2 + 1];
        float a = 0.f;
        #pragma unroll
        for (int c = 0; c < C_; c++) {
            float wc = sw[r][c];
            float2 rw = __ldg((const float2*)(ray0_w + (c * RH_ + o) * 2));
            a += wc * (p0 * rw.x + p1 * rw.y + __ldg(ray0_b + c * RH_ + o));
        }
        g_r1[r][o] = a > 0.f ? a : 0.f;
    }
}

// ============ k2: ray2v[r,o] — block per r; warp per 16 o's; lanes over h ============
__global__ void __launch_bounds__(256) k_rv(const float* __restrict__ ray2_w,
                                            const float* __restrict__ ray2_b) {
    int r = blockIdx.x;
    __shared__ float sw[C_];
    __shared__ float sr1[RH_];
    __shared__ float sbias[D_];
    int t = threadIdx.x;
    if (t < C_)  sw[t] = g_w[r][t];
    if (t < RH_) sr1[t] = g_r1[r][t];
    __syncthreads();
    if (t < D_) {
        float b = 0.f;
        #pragma unroll
        for (int c = 0; c < C_; c++) b += sw[c] * __ldg(ray2_b + c * D_ + t);
        sbias[t] = b;
    }
    __syncthreads();
    int warp = t >> 5, lane = t & 31;
    float r1a = sr1[lane], r1b = sr1[lane + 32];
    float acc[16];
    #pragma unroll
    for (int oi = 0; oi < 16; oi++) acc[oi] = 0.f;
    #pragma unroll
    for (int c = 0; c < C_; c++) {
        float wc = sw[c];
        #pragma unroll
        for (int oi = 0; oi < 16; oi++) {
            int o = warp * 16 + oi;
            const float* row = ray2_w + ((size_t)(c * D_ + o)) * RH_;
            float v0 = __ldg(row + lane), v1 = __ldg(row + lane + 32);
            acc[oi] += wc * (v0 * r1a + v1 * r1b);
        }
    }
    #pragma unroll
    for (int oi = 0; oi < 16; oi++) {
        float s = acc[oi];
        #pragma unroll
        for (int off = 16; off > 0; off >>= 1) s += __shfl_down_sync(0xffffffffu, s, off);
        if (lane == 0) g_rv[r][warp * 16 + oi] = s + sbias[warp * 16 + oi];
    }
}

// ============ k3: W2[r,h] / b1[r,h] — block per (r,kind); warp per 16 o's ============
__global__ void __launch_bounds__(256) k_w2b1(const float* __restrict__ fc2_w,
                                              const float* __restrict__ fc2_b,
                                              const float* __restrict__ b1_w,
                                              const float* __restrict__ b1_b) {
    int r = blockIdx.x & 15, kind = blockIdx.x >> 4;
    const float* Wc = kind ? b1_w : fc2_w;
    const float* bc = kind ? b1_b : fc2_b;
    __shared__ float sw[C_];
    __shared__ float sbias[HID_];
    int t = threadIdx.x;
    if (t < C_) sw[t] = g_w[r][t];
    __syncthreads();
    if (t < HID_) {
        float b = 0.f;
        #pragma unroll
        for (int c = 0; c < C_; c++) b += sw[c] * __ldg(bc + c * HID_ + t);
        sbias[t] = b;
    }
    __syncthreads();
    int warp = t >> 5, lane = t & 31;
    float4 rv4 = *(const float4*)&g_rv[r][lane * 4];
    float acc[16];
    #pragma unroll
    for (int oi = 0; oi < 16; oi++) acc[oi] = 0.f;
    #pragma unroll
    for (int c = 0; c < C_; c++) {
        float wc = sw[c];
        #pragma unroll
        for (int oi = 0; oi < 16; oi++) {
            int o = warp * 16 + oi;
            float4 v = __ldg((const float4*)(Wc + ((size_t)(c * HID_ + o)) * D_) + lane);
            acc[oi] += wc * (v.x * rv4.x + v.y * rv4.y + v.z * rv4.z + v.w * rv4.w);
        }
    }
    #pragma unroll
    for (int oi = 0; oi < 16; oi++) {
        float s = acc[oi];
        #pragma unroll
        for (int off = 16; off > 0; off >>= 1) s += __shfl_down_sync(0xffffffffu, s, off);
        if (lane == 0) {
            int o = warp * 16 + oi;
            if (kind) g_b1[r][o] = s + sbias[o]; else g_W2[r][o] = s + sbias[o];
        }
    }
}

// ============ k4: beff + P — 16 warps, one per r; P fill across all 512 ============
__global__ void k_prep(const float* __restrict__ b2_w, const float* __restrict__ b2_b) {
    int t = threadIdx.x;  // 512
    int warp = t >> 5, lane = t & 31;
    int r = warp;
    float4 rv4 = *(const float4*)&g_rv[r][lane * 4];
    float acc = 0.f;
    #pragma unroll
    for (int c = 0; c < C_; c++) {
        float wc = g_w[r][c];
        float4 bw = __ldg((const float4*)(b2_w + c * D_) + lane);
        acc += wc * (bw.x * rv4.x + bw.y * rv4.y + bw.z * rv4.z + bw.w * rv4.w);
        if (lane == 0) acc += wc * __ldg(b2_b + c);
    }
    float4 w24 = *(const float4*)&g_W2[r][lane * 4];
    float4 b14 = *(const float4*)&g_b1[r][lane * 4];
    acc += w24.x * b14.x + w24.y * b14.y + w24.z * b14.z + w24.w * b14.w;
    #pragma unroll
    for (int off = 16; off > 0; off >>= 1) acc += __shfl_down_sync(0xffffffffu, acc, off);
    if (lane == 0) g_beff[r] = acc;

    for (int idx = t; idx < CH_ * R_; idx += 512) {
        int ch = idx >> 4, rr = idx & 15;
        g_P[ch][rr] = g_w[rr][ch >> 7] * g_W2[rr][ch & 127];
    }
}

// ============ k5: THE big kernel — stream fc1_w (335 MB) -> Weff ============
__global__ void __launch_bounds__(256, 2) k_weff(const float* __restrict__ fc1_w) {
    int f = blockIdx.x;
    int warp = threadIdx.x >> 5, lane = threadIdx.x & 31;
    unsigned long long acc[8][4];
    #pragma unroll
    for (int rp = 0; rp < 8; rp++)
        #pragma unroll
        for (int j = 0; j < 4; j++) acc[rp][j] = 0ull;

    for (int cb = warp * 4; cb < CH_; cb += 32) {
        float4 v[4];
        #pragma unroll
        for (int q = 0; q < 4; q++) {
            int ch = cb + q;
            int c = ch >> 7, h = ch & 127;
            const float4* p = (const float4*)(fc1_w +
                (((size_t)c * 65536u + (size_t)h * 512u + (size_t)f) << 7)) + lane;
            v[q] = __ldg(p);
        }
        #pragma unroll
        for (int q = 0; q < 4; q++) {
            int ch = cb + q;
            const ulonglong2* pp = (const ulonglong2*)g_P[ch];
            ulonglong2 pA = __ldg(pp + 0);
            ulonglong2 pB = __ldg(pp + 1);
            ulonglong2 pC = __ldg(pp + 2);
            ulonglong2 pD = __ldg(pp + 3);
            unsigned long long vx = pk2(v[q].x, v[q].x), vy = pk2(v[q].y, v[q].y);
            unsigned long long vz = pk2(v[q].z, v[q].z), vw = pk2(v[q].w, v[q].w);
            FMA2(acc[0][0], vx, pA.x); FMA2(acc[0][1], vy, pA.x); FMA2(acc[0][2], vz, pA.x); FMA2(acc[0][3], vw, pA.x);
            FMA2(acc[1][0], vx, pA.y); FMA2(acc[1][1], vy, pA.y); FMA2(acc[1][2], vz, pA.y); FMA2(acc[1][3], vw, pA.y);
            FMA2(acc[2][0], vx, pB.x); FMA2(acc[2][1], vy, pB.x); FMA2(acc[2][2], vz, pB.x); FMA2(acc[2][3], vw, pB.x);
            FMA2(acc[3][0], vx, pB.y); FMA2(acc[3][1], vy, pB.y); FMA2(acc[3][2], vz, pB.y); FMA2(acc[3][3], vw, pB.y);
            FMA2(acc[4][0], vx, pC.x); FMA2(acc[4][1], vy, pC.x); FMA2(acc[4][2], vz, pC.x); FMA2(acc[4][3], vw, pC.x);
            FMA2(acc[5][0], vx, pC.y); FMA2(acc[5][1], vy, pC.y); FMA2(acc[5][2], vz, pC.y); FMA2(acc[5][3], vw, pC.y);
            FMA2(acc[6][0], vx, pD.x); FMA2(acc[6][1], vy, pD.x); FMA2(acc[6][2], vz, pD.x); FMA2(acc[6][3], vw, pD.x);
            FMA2(acc[7][0], vx, pD.y); FMA2(acc[7][1], vy, pD.y); FMA2(acc[7][2], vz, pD.y); FMA2(acc[7][3], vw, pD.y);
        }
    }
    // epilogue: multiply by rv[r][d] for this lane's d's, then reduce
    float accr[16];
    #pragma unroll
    for (int r = 0; r < 16; r++) accr[r] = 0.f;
    int d0 = lane * 4;
    #pragma unroll
    for (int rp = 0; rp < 8; rp++) {
        #pragma unroll
        for (int j = 0; j < 4; j++) {
            float a0, a1; upk2(acc[rp][j], a0, a1);
            accr[2 * rp]     += a0 * g_rv[2 * rp][d0 + j];
            accr[2 * rp + 1] += a1 * g_rv[2 * rp + 1][d0 + j];
        }
    }
    #pragma unroll
    for (int off = 16; off > 0; off >>= 1)
        #pragma unroll
        for (int r = 0; r < 16; r++)
            accr[r] += __shfl_down_sync(0xffffffffu, accr[r], off);
    __shared__ float sred[8][16];
    if (lane == 0) {
        #pragma unroll
        for (int r = 0; r < 16; r++) sred[warp][r] = accr[r];
    }
    __syncthreads();
    if (threadIdx.x < 16) {
        float s = 0.f;
        #pragma unroll
        for (int w = 0; w < 8; w++) s += sred[w][threadIdx.x];
        g_Weff[threadIdx.x][blockIdx.x] = s;
    }
}

// ============ k5b: add fc1_b bias contribution into Weff ============
__global__ void __launch_bounds__(128) k_weff_bias(const float* __restrict__ fc1_b) {
    int f = blockIdx.x, t = threadIdx.x;
    unsigned long long acc[8];
    #pragma unroll
    for (int rp = 0; rp < 8; rp++) acc[rp] = 0ull;
    for (int ch = t; ch < CH_; ch += 128) {
        float v = __ldg(fc1_b + (size_t)(ch >> 7) * 65536u + (size_t)(ch & 127) * 512u + f);
        unsigned long long vv = pk2(v, v);
        const ulonglong2* pp = (const ulonglong2*)g_P[ch];
        ulonglong2 pA = __ldg(pp + 0);
        ulonglong2 pB = __ldg(pp + 1);
        ulonglong2 pC = __ldg(pp + 2);
        ulonglong2 pD = __ldg(pp + 3);
        FMA2(acc[0], vv, pA.x); FMA2(acc[1], vv, pA.y);
        FMA2(acc[2], vv, pB.x); FMA2(acc[3], vv, pB.y);
        FMA2(acc[4], vv, pC.x); FMA2(acc[5], vv, pC.y);
        FMA2(acc[6], vv, pD.x); FMA2(acc[7], vv, pD.y);
    }
    float accr[16];
    #pragma unroll
    for (int rp = 0; rp < 8; rp++) upk2(acc[rp], accr[2 * rp], accr[2 * rp + 1]);
    #pragma unroll
    for (int off = 16; off > 0; off >>= 1)
        #pragma unroll
        for (int r = 0; r < 16; r++)
            accr[r] += __shfl_down_sync(0xffffffffu, accr[r], off);
    __shared__ float sred[4][16];
    int warp = t >> 5, lane = t & 31;
    if (lane == 0) {
        #pragma unroll
        for (int r = 0; r < 16; r++) sred[warp][r] = accr[r];
    }
    __syncthreads();
    if (t < 16) {
        float s = sred[0][t] + sred[1][t] + sred[2][t] + sred[3][t];
        g_Weff[t][f] += s;
    }
}

// ============ k6: fold Weff into base_w -> Wx (partials over f-chunks) ============
__global__ void __launch_bounds__(128) k_wx(const float* __restrict__ base_w) {
    __shared__ __align__(16) float sW[64][16];
    int i = blockIdx.x * 128 + threadIdx.x;
    int f0 = blockIdx.y * 64;
    for (int idx = threadIdx.x; idx < 64 * 16; idx += 128) {
        int ff = idx >> 4, r = idx & 15;
        sW[ff][r] = g_Weff[r][f0 + ff];
    }
    __syncthreads();
    unsigned long long acc[8];
    #pragma unroll
    for (int rp = 0; rp < 8; rp++) acc[rp] = 0ull;
    #pragma unroll 4
    for (int ff = 0; ff < 64; ff++) {
        float bw = __ldg(base_w + (size_t)(f0 + ff) * IN_ + i);
        unsigned long long b2 = pk2(bw, bw);
        const unsigned long long* pw = (const unsigned long long*)sW[ff];
        #pragma unroll
        for (int rp = 0; rp < 8; rp++) {
            unsigned long long t = pw[rp];
            FMA2(acc[rp], b2, t);
        }
    }
    float* o = &g_WxPart[blockIdx.y][i][0];
    #pragma unroll
    for (int rp = 0; rp < 8; rp++) {
        float a, b; upk2(acc[rp], a, b);
        o[2 * rp] = a; o[2 * rp + 1] = b;
    }
}

// ============ k6b: reduce Wx partials + cst[r] (warp-parallel) ============
__global__ void k_wx_reduce(const float* __restrict__ base_b) {
    int idx = blockIdx.x * 256 + threadIdx.x;  // 64 blocks x 256 = 16384 = IN_*R_
    if (idx < IN_ * R_) {
        int i = idx >> 4, r = idx & 15;
        float s = 0.f;
        #pragma unroll
        for (int p = 0; p < 8; p++) s += g_WxPart[p][i][r];
        g_WxT[i][r] = s;
    }
    if (blockIdx.x == 0) {
        int warp = threadIdx.x >> 5, lane = threadIdx.x & 31;
        #pragma unroll
        for (int rr = warp; rr < R_; rr += 8) {
            float a = 0.f;
            #pragma unroll
            for (int kk = 0; kk < 16; kk++) {
                int ff = kk * 32 + lane;
                a += g_Weff[rr][ff] * __ldg(base_b + ff);
            }
            #pragma unroll
            for (int off = 16; off > 0; off >>= 1) a += __shfl_down_sync(0xffffffffu, a, off);
            if (lane == 0) g_cst[rr] = g_beff[rr] + a;
        }
    }
}

// ============ k7: out[r,b] = x[b,:] . Wx[r,:] + cst[r]; 4 b per warp ============
#define FMA8(J, XS, WA, WB, WC, WD) \
    FMA2(acc[J][0], XS, WA.x); FMA2(acc[J][1], XS, WA.y); \
    FMA2(acc[J][2], XS, WB.x); FMA2(acc[J][3], XS, WB.y); \
    FMA2(acc[J][4], XS, WC.x); FMA2(acc[J][5], XS, WC.y); \
    FMA2(acc[J][6], XS, WD.x); FMA2(acc[J][7], XS, WD.y);

#define DO_DI(DI, COMP) { \
    const ulonglong2* wr = (const ulonglong2*)g_WxT[ib + DI]; \
    ulonglong2 wA = __ldg(wr + 0), wB = __ldg(wr + 1), wC = __ldg(wr + 2), wD = __ldg(wr + 3); \
    unsigned long long x0 = pk2(xv0.COMP, xv0.COMP); \
    unsigned long long x1 = pk2(xv1.COMP, xv1.COMP); \
    unsigned long long x2 = pk2(xv2.COMP, xv2.COMP); \
    unsigned long long x3 = pk2(xv3.COMP, xv3.COMP); \
    FMA8(0, x0, wA, wB, wC, wD) \
    FMA8(1, x1, wA, wB, wC, wD) \
    FMA8(2, x2, wA, wB, wC, wD) \
    FMA8(3, x3, wA, wB, wC, wD) \
}

__global__ void __launch_bounds__(256) k_out(const float* __restrict__ x,
                                             float* __restrict__ out, int write_raw) {
    int warp = threadIdx.x >> 5, lane = threadIdx.x & 31;
    int b0 = (blockIdx.x * 8 + warp) * 4;
    unsigned long long acc[4][8];
    #pragma unroll
    for (int j = 0; j < 4; j++)
        #pragma unroll
        for (int rp = 0; rp < 8; rp++) acc[j][rp] = 0ull;

    #pragma unroll
    for (int k = 0; k < 8; k++) {
        float4 xv0 = __ldg((const float4*)(x + (size_t)(b0 + 0) * IN_) + k * 32 + lane);
        float4 xv1 = __ldg((const float4*)(x + (size_t)(b0 + 1) * IN_) + k * 32 + lane);
        float4 xv2 = __ldg((const float4*)(x + (size_t)(b0 + 2) * IN_) + k * 32 + lane);
        float4 xv3 = __ldg((const float4*)(x + (size_t)(b0 + 3) * IN_) + k * 32 + lane);
        int ib = (k * 32 + lane) * 4;
        DO_DI(0, x)
        DO_DI(1, y)
        DO_DI(2, z)
        DO_DI(3, w)
    }
    float accr[4][16];
    #pragma unroll
    for (int j = 0; j < 4; j++)
        #pragma unroll
        for (int rp = 0; rp < 8; rp++) upk2(acc[j][rp], accr[j][2 * rp], accr[j][2 * rp + 1]);
    #pragma unroll
    for (int off = 16; off > 0; off >>= 1)
        #pragma unroll
        for (int j = 0; j < 4; j++)
            #pragma unroll
            for (int r = 0; r < 16; r++)
                accr[j][r] += __shfl_down_sync(0xffffffffu, accr[j][r], off);
    if (lane == 0) {
        #pragma unroll
        for (int j = 0; j < 4; j++) {
            #pragma unroll
            for (int r = 0; r < 16; r++) {
                float v = accr[j][r] + g_cst[r];
                out[r * B_ + b0 + j] = 1.f / (1.f + expf(-v));
                if (write_raw) out[R_ * B_ + r * B_ + b0 + j] = v;
            }
        }
    }
}

// ---------------- launcher ----------------
extern "C" void kernel_launch(void* const* d_in, const int* in_sizes, int n_in,
                              void* d_out, int out_size) {
    const float* x      = (const float*)d_in[0];
    const float* pref   = (const float*)d_in[1];
    const float* base_w = (const float*)d_in[2];
    const float* base_b = (const float*)d_in[3];
    const float* wm1_w  = (const float*)d_in[4];
    const float* wm1_b  = (const float*)d_in[5];
    const float* wm2_w  = (const float*)d_in[6];
    const float* wm2_b  = (const float*)d_in[7];
    const float* ray0_w = (const float*)d_in[8];
    const float* ray0_b = (const float*)d_in[9];
    const float* ray2_w = (const float*)d_in[10];
    const float* ray2_b = (const float*)d_in[11];
    const float* fc1_w  = (const float*)d_in[12];
    const float* fc1_b  = (const float*)d_in[13];
    const float* b1_w   = (const float*)d_in[14];
    const float* b1_b   = (const float*)d_in[15];
    const float* fc2_w  = (const float*)d_in[16];
    const float* fc2_b  = (const float*)d_in[17];
    const float* b2_w   = (const float*)d_in[18];
    const float* b2_b   = (const float*)d_in[19];
    float* out = (float*)d_out;
    int write_raw = (out_size >= 2 * R_ * B_) ? 1 : 0;

    k_tiny1<<<1, 256>>>(pref, wm1_w, wm1_b, wm2_w, wm2_b, ray0_w, ray0_b);
    k_rv<<<R_, 256>>>(ray2_w, ray2_b);
    k_w2b1<<<32, 256>>>(fc2_w, fc2_b, b1_w, b1_b);
    k_prep<<<1, 512>>>(b2_w, b2_b);
    k_weff<<<F_, 256>>>(fc1_w);
    k_weff_bias<<<F_, 128>>>(fc1_b);
    dim3 g6(8, 8);
    k_wx<<<g6, 128>>>(base_w);
    k_wx_reduce<<<64, 256>>>(base_b);
    k_out<<<B_ / 32, 256>>>(x, out, write_raw);
}